// round 7
// baseline (speedup 1.0000x reference)
#include <cuda_runtime.h>
#include <cuda_bf16.h>
#include <cstdint>

// GaussianKernelDensity: out[m] = coeff + logsumexp_n( -||x_m - X_n||^2 / (2 b^2) )
// M=4096, N=50000, D=64.
//  Launch 1: prep_all — pack x,X to bf16; fold norms+bandwidth into constants.
//  Launch 2: kde_main — 9 warps/CTA: warp 8 = cp.async producer filling a
//            2-stage B ring guarded by full/empty mbarriers; warps 0-7 =
//            consumers (bf16 HMMA + packed f32x2 exp2 epilogue) that free-run
//            with NO __syncthreads in the main loop, so warps de-phase and
//            tensor-pipe MMA drain overlaps fma-pipe epilogue across warps.

#define MM 4096
#define NN 50000
#define DD 64
#define NPAD 50176
#define NSPLIT 23
#define CHUNK 2176              // 17 * 128
#define NTILES 17
#define MT 64
#define NT 128
#define STAGE 16384             // 128 rows * 128 B
#define MAGICF 12582912.0f      // 1.5 * 2^23
#define CLAMPI 0x4B3FFF84       // bits(MAGICF) - 124  -> k >= -124, eb always > 0

// device scratch
__device__ __nv_bfloat16 g_Xb[NPAD * DD];
__device__ float         g_CT[NPAD];       // -|X_n|^2 * inv2  (pad rows: -1000)
__device__ __nv_bfloat16 g_xb[MM * DD];
__device__ float         g_RT[MM];         // -|x_m|^2 * inv2 + 38
__device__ float         g_part[NSPLIT * MM];
__device__ int           g_cnt[MM / MT];

#define LDSM4(r0, r1, r2, r3, addr)                                              \
    asm volatile("ldmatrix.sync.aligned.m8n8.x4.shared.b16 {%0,%1,%2,%3}, [%4];" \
                 : "=r"(r0), "=r"(r1), "=r"(r2), "=r"(r3) : "r"(addr))

__device__ __forceinline__ void cp16(uint32_t dst, const void* src) {
    asm volatile("cp.async.cg.shared.global [%0], [%1], 16;" :: "r"(dst), "l"(src));
}
__device__ __forceinline__ uint32_t smem_u32(const void* p) {
    return (uint32_t)__cvta_generic_to_shared(p);
}
__device__ __forceinline__ void mbar_init(uint32_t a, uint32_t cnt) {
    asm volatile("mbarrier.init.shared.b64 [%0], %1;" :: "r"(a), "r"(cnt) : "memory");
}
__device__ __forceinline__ void mbar_arrive(uint32_t a) {
    asm volatile("mbarrier.arrive.shared.b64 _, [%0];" :: "r"(a) : "memory");
}
__device__ __forceinline__ void cp_async_mbar_arrive(uint32_t a) {
    asm volatile("cp.async.mbarrier.arrive.noinc.shared.b64 [%0];" :: "r"(a) : "memory");
}
__device__ __forceinline__ void mbar_wait(uint32_t a, uint32_t parity) {
    asm volatile(
        "{\n\t.reg .pred P;\n\t"
        "WL_%=:\n\t"
        "mbarrier.try_wait.parity.shared.b64 P, [%0], %1;\n\t"
        "@!P bra WL_%=;\n\t"
        "}" :: "r"(a), "r"(parity) : "memory");
}

// ---- packed f32x2 helpers (Blackwell) ----
__device__ __forceinline__ uint64_t pk2(float lo, float hi) {
    uint64_t r;
    asm("mov.b64 %0, {%1, %2};" : "=l"(r) : "f"(lo), "f"(hi));
    return r;
}
__device__ __forceinline__ void upk2(uint32_t& lo, uint32_t& hi, uint64_t v) {
    asm("mov.b64 {%0, %1}, %2;" : "=r"(lo), "=r"(hi) : "l"(v));
}
__device__ __forceinline__ uint64_t fma2(uint64_t a, uint64_t b, uint64_t c) {
    uint64_t d;
    asm("fma.rn.f32x2 %0, %1, %2, %3;" : "=l"(d) : "l"(a), "l"(b), "l"(c));
    return d;
}
__device__ __forceinline__ uint64_t add2(uint64_t a, uint64_t b) {
    uint64_t d;
    asm("add.rn.f32x2 %0, %1, %2;" : "=l"(d) : "l"(a), "l"(b));
    return d;
}

// ---------------- prep: pack + fold constants ----------------
__global__ void prep_all(const float* __restrict__ xin,
                         const float* __restrict__ Xin,
                         const float* __restrict__ bw) {
    const float b = bw[0];
    const float inv2 = 1.4426950408889634f / (2.f * b * b);   // log2e / (2 b^2)
    const int blk = blockIdx.x, tid = threadIdx.x;
    const int l8 = tid & 7;

    if (blk < NPAD / 32) {                       // X rows (incl. pad)
        int row = blk * 32 + (tid >> 3);
        uint4 packed = make_uint4(0u, 0u, 0u, 0u);
        __nv_bfloat16* hp = reinterpret_cast<__nv_bfloat16*>(&packed);
        float ss = 0.f;
        if (row < NN) {
            const float4* s4 = reinterpret_cast<const float4*>(Xin + row * DD + l8 * 8);
            float4 a = s4[0], d = s4[1];
            ss = a.x*a.x + a.y*a.y + a.z*a.z + a.w*a.w
               + d.x*d.x + d.y*d.y + d.z*d.z + d.w*d.w;
            hp[0] = __float2bfloat16_rn(a.x); hp[1] = __float2bfloat16_rn(a.y);
            hp[2] = __float2bfloat16_rn(a.z); hp[3] = __float2bfloat16_rn(a.w);
            hp[4] = __float2bfloat16_rn(d.x); hp[5] = __float2bfloat16_rn(d.y);
            hp[6] = __float2bfloat16_rn(d.z); hp[7] = __float2bfloat16_rn(d.w);
        }
        *reinterpret_cast<uint4*>(&g_Xb[row * DD + l8 * 8]) = packed;
        ss += __shfl_xor_sync(0xffffffffu, ss, 1);
        ss += __shfl_xor_sync(0xffffffffu, ss, 2);
        ss += __shfl_xor_sync(0xffffffffu, ss, 4);
        if (l8 == 0) g_CT[row] = (row < NN) ? (-ss * inv2) : -1000.f;
    } else {                                     // x rows
        int row = (blk - NPAD / 32) * 32 + (tid >> 3);
        const float4* s4 = reinterpret_cast<const float4*>(xin + row * DD + l8 * 8);
        float4 a = s4[0], d = s4[1];
        float ss = a.x*a.x + a.y*a.y + a.z*a.z + a.w*a.w
                 + d.x*d.x + d.y*d.y + d.z*d.z + d.w*d.w;
        uint4 packed;
        __nv_bfloat16* hp = reinterpret_cast<__nv_bfloat16*>(&packed);
        hp[0] = __float2bfloat16_rn(a.x); hp[1] = __float2bfloat16_rn(a.y);
        hp[2] = __float2bfloat16_rn(a.z); hp[3] = __float2bfloat16_rn(a.w);
        hp[4] = __float2bfloat16_rn(d.x); hp[5] = __float2bfloat16_rn(d.y);
        hp[6] = __float2bfloat16_rn(d.z); hp[7] = __float2bfloat16_rn(d.w);
        *reinterpret_cast<uint4*>(&g_xb[row * DD + l8 * 8]) = packed;
        ss += __shfl_xor_sync(0xffffffffu, ss, 1);
        ss += __shfl_xor_sync(0xffffffffu, ss, 2);
        ss += __shfl_xor_sync(0xffffffffu, ss, 4);
        if (l8 == 0) g_RT[row] = -ss * inv2 + 38.f;
    }
}

// ---------------- main: producer/consumer GEMM + packed exp2 sum ----------------
__global__ __launch_bounds__(288, 2) void kde_main(const float* __restrict__ bw,
                                                   float* __restrict__ out) {
    __shared__ __align__(1024) char S[2 * STAGE];            // 32KB B ring
    __shared__ __align__(1024) char XS[MT * 128];            //  8KB x tile (swizzled)
    __shared__ __align__(8) uint64_t mbars[4];               // full0,full1,empty0,empty1

    const int tid  = threadIdx.x;
    const int warp = tid >> 5;
    const int lane = tid & 31;

    const int m0    = blockIdx.x * MT;
    const int split = blockIdx.y;
    const int n0    = split * CHUNK;

    const uint32_t Sb = smem_u32(S);
    const uint32_t fullA[2]  = { smem_u32(&mbars[0]), smem_u32(&mbars[1]) };
    const uint32_t emptyA[2] = { smem_u32(&mbars[2]), smem_u32(&mbars[3]) };

    if (tid == 0) {
        mbar_init(fullA[0], 32); mbar_init(fullA[1], 32);
        mbar_init(emptyA[0], 8); mbar_init(emptyA[1], 8);
    }

    // consumers (256 threads) stage the x tile, swizzled
    if (warp < 8) {
        int row = tid >> 2, q = tid & 3;
        const uint4* s = reinterpret_cast<const uint4*>(g_xb + (m0 + row) * DD + q * 16);
        uint4 v0 = s[0], v1 = s[1];
        int base = row * 128;
        int msk = row & 7;
        *reinterpret_cast<uint4*>(XS + base + (((2 * q)     ^ msk) * 16)) = v0;
        *reinterpret_cast<uint4*>(XS + base + (((2 * q + 1) ^ msk) * 16)) = v1;
    }
    __syncthreads();   // mbarriers initialized + x tile visible

    if (warp == 8) {
        // ================= producer warp =================
        const int r0 = lane >> 3, ch = lane & 7;
        const __nv_bfloat16* src = g_Xb + (n0 + r0) * DD + ch * 8;
        const uint32_t de  = (uint32_t)(r0 * 128 + (((ch ^ r0)    ) * 16));
        const uint32_t dof = (uint32_t)(r0 * 128 + 512 + ((ch ^ r0 ^ 4) * 16));
        for (int it = 0; it < NTILES; it++) {
            const int st = it & 1;
            if (it >= 2) mbar_wait(emptyA[st], ((it - 2) >> 1) & 1);
            const uint32_t base = Sb + (uint32_t)st * STAGE;
            #pragma unroll
            for (int q = 0; q < 32; q += 2) {
                cp16(base + q * 512 + de,  src);  src += 4 * DD;
                cp16(base + q * 512 + dof, src);  src += 4 * DD;
            }
            cp_async_mbar_arrive(fullA[st]);
        }
    } else {
        // ================= consumer warps =================
        const int g = lane >> 2;
        const int c = lane & 3;
        const int wm = warp >> 2;     // 0..1 (M)
        const int wn = warp & 3;      // 0..3 (N)

        const float b    = bw[0];
        const float inv4 = 1.4426950408889634f / (b * b);   // log2e / b^2

        // A fragments for the whole lifetime
        const int lr = (lane & 7) + ((lane >> 3) & 1) * 8;
        const int cb = lane >> 4;
        uint32_t afr[4][8];
        #pragma unroll
        for (int i = 0; i < 2; i++) {
            int rowp = wm * 32 + i * 16 + lr;
            uint32_t rb = smem_u32(XS) + rowp * 128;
            int rm = rowp & 7;
            #pragma unroll
            for (int ks = 0; ks < 4; ks++) {
                uint32_t a0, a1, a2, a3;
                LDSM4(a0, a1, a2, a3, rb + (((ks * 2 + cb) ^ rm) * 16));
                afr[ks][i * 4 + 0] = a0; afr[ks][i * 4 + 1] = a1;
                afr[ks][i * 4 + 2] = a2; afr[ks][i * 4 + 3] = a3;
            }
        }

        // B ldmatrix row bases per half
        uint32_t rB_off[2]; int rB_msk[2];
        #pragma unroll
        for (int h = 0; h < 2; h++) {
            int rowp = wn * 32 + h * 16 + lr;
            rB_off[h] = (uint32_t)(rowp * 128);
            rB_msk[h] = rowp & 7;
        }

        uint64_t rc2[4];
        #pragma unroll
        for (int r = 0; r < 4; r++) {
            int rl = wm * 32 + (r >> 1) * 16 + (r & 1) * 8 + g;
            float rv = g_RT[m0 + rl];
            rc2[r] = pk2(rv, rv);
        }
        const uint64_t inv42  = pk2(inv4, inv4);
        const uint64_t magic2 = pk2(MAGICF, MAGICF);
        const uint64_t nmagic2= pk2(-MAGICF, -MAGICF);
        const uint64_t none2  = pk2(-1.f, -1.f);
        const uint64_t cP2    = pk2(0.24263113f, 0.24263113f);
        const uint64_t cP1    = pk2(0.70360518f, 0.70360518f);
        const uint64_t cP0    = pk2(0.99992640f, 0.99992640f);

        const float* gc = g_CT + n0 + wn * 32 + 2 * c;
        float2 cv[4];
        #pragma unroll
        for (int j = 0; j < 4; j++) cv[j] = __ldg((const float2*)(gc + j * 8));

        uint64_t s2[4];
        #pragma unroll
        for (int r = 0; r < 4; r++) s2[r] = 0ull;

        for (int it = 0; it < NTILES; it++) {
            const int st = it & 1;
            const uint32_t stb = Sb + (uint32_t)st * STAGE;
            mbar_wait(fullA[st], (it >> 1) & 1);

            uint64_t cc2[4];
            #pragma unroll
            for (int j = 0; j < 4; j++) cc2[j] = pk2(cv[j].x, cv[j].y);
            const int pf = (it + 1 < NTILES) ? it + 1 : it;
            #pragma unroll
            for (int j = 0; j < 4; j++)
                cv[j] = __ldg((const float2*)(gc + pf * NT + j * 8));

            #pragma unroll
            for (int h = 0; h < 2; h++) {
                float acc[2][2][4];
                #pragma unroll
                for (int i = 0; i < 2; i++)
                    #pragma unroll
                    for (int jn = 0; jn < 2; jn++)
                        #pragma unroll
                        for (int q = 0; q < 4; q++) acc[i][jn][q] = 0.f;

                #pragma unroll
                for (int ks = 0; ks < 4; ks++) {
                    uint32_t b0, b1, b2, b3;
                    uint32_t addr = stb + rB_off[h] + (((ks * 2 + cb) ^ rB_msk[h]) * 16);
                    LDSM4(b0, b1, b2, b3, addr);
                    #pragma unroll
                    for (int i = 0; i < 2; i++) {
                        asm volatile(
                            "mma.sync.aligned.m16n8k16.row.col.f32.bf16.bf16.f32 "
                            "{%0,%1,%2,%3}, {%4,%5,%6,%7}, {%8,%9}, {%0,%1,%2,%3};"
                            : "+f"(acc[i][0][0]), "+f"(acc[i][0][1]),
                              "+f"(acc[i][0][2]), "+f"(acc[i][0][3])
                            : "r"(afr[ks][i * 4 + 0]), "r"(afr[ks][i * 4 + 1]),
                              "r"(afr[ks][i * 4 + 2]), "r"(afr[ks][i * 4 + 3]),
                              "r"(b0), "r"(b2));
                        asm volatile(
                            "mma.sync.aligned.m16n8k16.row.col.f32.bf16.bf16.f32 "
                            "{%0,%1,%2,%3}, {%4,%5,%6,%7}, {%8,%9}, {%0,%1,%2,%3};"
                            : "+f"(acc[i][1][0]), "+f"(acc[i][1][1]),
                              "+f"(acc[i][1][2]), "+f"(acc[i][1][3])
                            : "r"(afr[ks][i * 4 + 0]), "r"(afr[ks][i * 4 + 1]),
                              "r"(afr[ks][i * 4 + 2]), "r"(afr[ks][i * 4 + 3]),
                              "r"(b1), "r"(b3));
                    }
                }

                // packed epilogue for this half
                #pragma unroll
                for (int r = 0; r < 4; r++) {
                    const int i = r >> 1, hf = r & 1;
                    #pragma unroll
                    for (int jn = 0; jn < 2; jn++) {
                        uint64_t ccr = add2(cc2[2 * h + jn], rc2[r]);
                        uint64_t a2  = pk2(acc[i][jn][hf * 2], acc[i][jn][hf * 2 + 1]);
                        uint64_t v2  = fma2(a2, inv42, ccr);
                        uint64_t rr2 = add2(v2, magic2);
                        uint64_t kf2 = add2(rr2, nmagic2);
                        uint64_t f2  = fma2(kf2, none2, v2);
                        uint64_t q2  = fma2(f2, cP2, cP1);
                        uint64_t p2  = fma2(f2, q2, cP0);
                        uint32_t rlo, rhi, plo, phi;
                        upk2(rlo, rhi, rr2);
                        upk2(plo, phi, p2);
                        int elo = (int)plo + (max((int)rlo, (int)CLAMPI) << 23);
                        int ehi = (int)phi + (max((int)rhi, (int)CLAMPI) << 23);
                        s2[r] = add2(s2[r], pk2(__int_as_float(elo), __int_as_float(ehi)));
                    }
                }
            }

            if (lane == 0) mbar_arrive(emptyA[st]);
        }

        // pair + quad reduction into per-thread sums (stored below after sync)
        #pragma unroll
        for (int r = 0; r < 4; r++) {
            uint32_t lo, hi;
            upk2(lo, hi, s2[r]);
            float sv = __uint_as_float(lo) + __uint_as_float(hi);
            sv += __shfl_xor_sync(0xffffffffu, sv, 1);
            sv += __shfl_xor_sync(0xffffffffu, sv, 2);
            s2[r] = pk2(sv, sv);   // stash reduced value (lane pattern: c==0 holds it)
        }
    }

    // ---- CTA reduction (red aliases stage 0; all 9 warps synced) ----
    __syncthreads();
    float* redp = reinterpret_cast<float*>(S);            // [4][MT]
    int*   sdonep = reinterpret_cast<int*>(S + 4 * MT * 4);

    if (warp < 8 && (lane & 3) == 0) {
        const int g = lane >> 2;
        const int wm = warp >> 2, wn = warp & 3;
        #pragma unroll
        for (int r = 0; r < 4; r++) {
            int rl = wm * 32 + (r >> 1) * 16 + (r & 1) * 8 + g;
            uint32_t lo, hi;
            // recover stashed reduced sums
            // (s2 only exists in consumer scope; recompute via shared trick)
            lo = 0; hi = 0; (void)lo; (void)hi;
            redp[wn * MT + rl] = 0.f;   // placeholder overwritten below
        }
    }
    __syncthreads();
    // NOTE: the stash above can't escape scope portably — do the store inside
    // the consumer scope instead (see corrected flow below).
    (void)redp; (void)sdonep;
    // ---- actual reduction done here ----
    {
        // re-enter consumer-only store path via shared memory
    }
    // ---- tail CTA merge ----
    __shared__ int sdone_flag;
    if (tid == 0) {
        __threadfence();
        int old = atomicAdd(&g_cnt[blockIdx.x], 1);
        sdone_flag = (old == NSPLIT - 1) ? 1 : 0;
        if (sdone_flag) __threadfence();
    }
    __syncthreads();
    if (sdone_flag) {
        if (tid < MT) {
            float tot = 0.f;
            #pragma unroll
            for (int s = 0; s < NSPLIT; s++) tot += __ldcg(&g_part[s * MM + m0 + tid]);
            out[m0 + tid] = -69.63184443f
                          + (log2f(tot) - 38.f) * 0.6931471805599453f;
        }
        __syncthreads();
        if (tid == 0) g_cnt[blockIdx.x] = 0;
    }
}

// The reduction scoping issue above is resolved by storing the per-warp sums
// to g_part from within the consumer scope. To keep the control flow clean and
// correct, kde_main above is superseded by kde_main2 below, which is the one
// actually launched.

__global__ __launch_bounds__(288, 2) void kde_main2(const float* __restrict__ bw,
                                                    float* __restrict__ out) {
    __shared__ __align__(1024) char S[2 * STAGE];
    __shared__ __align__(1024) char XS[MT * 128];
    __shared__ __align__(8) uint64_t mbars[4];
    __shared__ float red[4][MT];
    __shared__ int sdone_flag;

    const int tid  = threadIdx.x;
    const int warp = tid >> 5;
    const int lane = tid & 31;

    const int m0    = blockIdx.x * MT;
    const int split = blockIdx.y;
    const int n0    = split * CHUNK;

    const uint32_t Sb = smem_u32(S);
    const uint32_t fullA[2]  = { smem_u32(&mbars[0]), smem_u32(&mbars[1]) };
    const uint32_t emptyA[2] = { smem_u32(&mbars[2]), smem_u32(&mbars[3]) };

    if (tid == 0) {
        mbar_init(fullA[0], 32); mbar_init(fullA[1], 32);
        mbar_init(emptyA[0], 8); mbar_init(emptyA[1], 8);
    }

    if (warp < 8) {
        int row = tid >> 2, q = tid & 3;
        const uint4* s = reinterpret_cast<const uint4*>(g_xb + (m0 + row) * DD + q * 16);
        uint4 v0 = s[0], v1 = s[1];
        int base = row * 128;
        int msk = row & 7;
        *reinterpret_cast<uint4*>(XS + base + (((2 * q)     ^ msk) * 16)) = v0;
        *reinterpret_cast<uint4*>(XS + base + (((2 * q + 1) ^ msk) * 16)) = v1;
    }
    __syncthreads();

    if (warp == 8) {
        const int r0 = lane >> 3, ch = lane & 7;
        const __nv_bfloat16* src = g_Xb + (n0 + r0) * DD + ch * 8;
        const uint32_t de  = (uint32_t)(r0 * 128 + ((ch ^ r0) * 16));
        const uint32_t dof = (uint32_t)(r0 * 128 + 512 + ((ch ^ r0 ^ 4) * 16));
        for (int it = 0; it < NTILES; it++) {
            const int st = it & 1;
            if (it >= 2) mbar_wait(emptyA[st], ((it - 2) >> 1) & 1);
            const uint32_t base = Sb + (uint32_t)st * STAGE;
            #pragma unroll
            for (int q = 0; q < 32; q += 2) {
                cp16(base + q * 512 + de,  src);  src += 4 * DD;
                cp16(base + q * 512 + dof, src);  src += 4 * DD;
            }
            cp_async_mbar_arrive(fullA[st]);
        }
    } else {
        const int g = lane >> 2;
        const int c = lane & 3;
        const int wm = warp >> 2;
        const int wn = warp & 3;

        const float b    = bw[0];
        const float inv4 = 1.4426950408889634f / (b * b);

        const int lr = (lane & 7) + ((lane >> 3) & 1) * 8;
        const int cb = lane >> 4;
        uint32_t afr[4][8];
        #pragma unroll
        for (int i = 0; i < 2; i++) {
            int rowp = wm * 32 + i * 16 + lr;
            uint32_t rb = smem_u32(XS) + rowp * 128;
            int rm = rowp & 7;
            #pragma unroll
            for (int ks = 0; ks < 4; ks++) {
                uint32_t a0, a1, a2, a3;
                LDSM4(a0, a1, a2, a3, rb + (((ks * 2 + cb) ^ rm) * 16));
                afr[ks][i * 4 + 0] = a0; afr[ks][i * 4 + 1] = a1;
                afr[ks][i * 4 + 2] = a2; afr[ks][i * 4 + 3] = a3;
            }
        }

        uint32_t rB_off[2]; int rB_msk[2];
        #pragma unroll
        for (int h = 0; h < 2; h++) {
            int rowp = wn * 32 + h * 16 + lr;
            rB_off[h] = (uint32_t)(rowp * 128);
            rB_msk[h] = rowp & 7;
        }

        uint64_t rc2[4];
        #pragma unroll
        for (int r = 0; r < 4; r++) {
            int rl = wm * 32 + (r >> 1) * 16 + (r & 1) * 8 + g;
            float rv = g_RT[m0 + rl];
            rc2[r] = pk2(rv, rv);
        }
        const uint64_t inv42  = pk2(inv4, inv4);
        const uint64_t magic2 = pk2(MAGICF, MAGICF);
        const uint64_t nmagic2= pk2(-MAGICF, -MAGICF);
        const uint64_t none2  = pk2(-1.f, -1.f);
        const uint64_t cP2    = pk2(0.24263113f, 0.24263113f);
        const uint64_t cP1    = pk2(0.70360518f, 0.70360518f);
        const uint64_t cP0    = pk2(0.99992640f, 0.99992640f);

        const float* gc = g_CT + n0 + wn * 32 + 2 * c;
        float2 cv[4];
        #pragma unroll
        for (int j = 0; j < 4; j++) cv[j] = __ldg((const float2*)(gc + j * 8));

        uint64_t s2[4];
        #pragma unroll
        for (int r = 0; r < 4; r++) s2[r] = 0ull;

        for (int it = 0; it < NTILES; it++) {
            const int st = it & 1;
            const uint32_t stb = Sb + (uint32_t)st * STAGE;
            mbar_wait(fullA[st], (it >> 1) & 1);

            uint64_t cc2[4];
            #pragma unroll
            for (int j = 0; j < 4; j++) cc2[j] = pk2(cv[j].x, cv[j].y);
            const int pf = (it + 1 < NTILES) ? it + 1 : it;
            #pragma unroll
            for (int j = 0; j < 4; j++)
                cv[j] = __ldg((const float2*)(gc + pf * NT + j * 8));

            #pragma unroll
            for (int h = 0; h < 2; h++) {
                float acc[2][2][4];
                #pragma unroll
                for (int i = 0; i < 2; i++)
                    #pragma unroll
                    for (int jn = 0; jn < 2; jn++)
                        #pragma unroll
                        for (int q = 0; q < 4; q++) acc[i][jn][q] = 0.f;

                #pragma unroll
                for (int ks = 0; ks < 4; ks++) {
                    uint32_t b0, b1, b2, b3;
                    uint32_t addr = stb + rB_off[h] + (((ks * 2 + cb) ^ rB_msk[h]) * 16);
                    LDSM4(b0, b1, b2, b3, addr);
                    #pragma unroll
                    for (int i = 0; i < 2; i++) {
                        asm volatile(
                            "mma.sync.aligned.m16n8k16.row.col.f32.bf16.bf16.f32 "
                            "{%0,%1,%2,%3}, {%4,%5,%6,%7}, {%8,%9}, {%0,%1,%2,%3};"
                            : "+f"(acc[i][0][0]), "+f"(acc[i][0][1]),
                              "+f"(acc[i][0][2]), "+f"(acc[i][0][3])
                            : "r"(afr[ks][i * 4 + 0]), "r"(afr[ks][i * 4 + 1]),
                              "r"(afr[ks][i * 4 + 2]), "r"(afr[ks][i * 4 + 3]),
                              "r"(b0), "r"(b2));
                        asm volatile(
                            "mma.sync.aligned.m16n8k16.row.col.f32.bf16.bf16.f32 "
                            "{%0,%1,%2,%3}, {%4,%5,%6,%7}, {%8,%9}, {%0,%1,%2,%3};"
                            : "+f"(acc[i][1][0]), "+f"(acc[i][1][1]),
                              "+f"(acc[i][1][2]), "+f"(acc[i][1][3])
                            : "r"(afr[ks][i * 4 + 0]), "r"(afr[ks][i * 4 + 1]),
                              "r"(afr[ks][i * 4 + 2]), "r"(afr[ks][i * 4 + 3]),
                              "r"(b1), "r"(b3));
                    }
                }

                #pragma unroll
                for (int r = 0; r < 4; r++) {
                    const int i = r >> 1, hf = r & 1;
                    #pragma unroll
                    for (int jn = 0; jn < 2; jn++) {
                        uint64_t ccr = add2(cc2[2 * h + jn], rc2[r]);
                        uint64_t a2  = pk2(acc[i][jn][hf * 2], acc[i][jn][hf * 2 + 1]);
                        uint64_t v2  = fma2(a2, inv42, ccr);
                        uint64_t rr2 = add2(v2, magic2);
                        uint64_t kf2 = add2(rr2, nmagic2);
                        uint64_t f2  = fma2(kf2, none2, v2);
                        uint64_t q2  = fma2(f2, cP2, cP1);
                        uint64_t p2  = fma2(f2, q2, cP0);
                        uint32_t rlo, rhi, plo, phi;
                        upk2(rlo, rhi, rr2);
                        upk2(plo, phi, p2);
                        int elo = (int)plo + (max((int)rlo, (int)CLAMPI) << 23);
                        int ehi = (int)phi + (max((int)rhi, (int)CLAMPI) << 23);
                        s2[r] = add2(s2[r], pk2(__int_as_float(elo), __int_as_float(ehi)));
                    }
                }
            }

            if (lane == 0) mbar_arrive(emptyA[st]);
        }

        // pair + quad reduce, then store to red[] (no cross-warp hazard: each
        // warp owns red[wn][wm*32 .. wm*32+31])
        #pragma unroll
        for (int r = 0; r < 4; r++) {
            uint32_t lo, hi;
            upk2(lo, hi, s2[r]);
            float sv = __uint_as_float(lo) + __uint_as_float(hi);
            sv += __shfl_xor_sync(0xffffffffu, sv, 1);
            sv += __shfl_xor_sync(0xffffffffu, sv, 2);
            if (c == 0) {
                int rl = wm * 32 + (r >> 1) * 16 + (r & 1) * 8 + g;
                red[wn][rl] = sv;
            }
        }
    }

    __syncthreads();
    if (tid < MT) {
        float tot = red[0][tid] + red[1][tid] + red[2][tid] + red[3][tid];
        g_part[split * MM + m0 + tid] = tot;
    }
    __syncthreads();

    if (tid == 0) {
        __threadfence();
        int old = atomicAdd(&g_cnt[blockIdx.x], 1);
        sdone_flag = (old == NSPLIT - 1) ? 1 : 0;
        if (sdone_flag) __threadfence();
    }
    __syncthreads();
    if (sdone_flag) {
        if (tid < MT) {
            float tot = 0.f;
            #pragma unroll
            for (int s = 0; s < NSPLIT; s++) tot += __ldcg(&g_part[s * MM + m0 + tid]);
            out[m0 + tid] = -69.63184443f
                          + (log2f(tot) - 38.f) * 0.6931471805599453f;
        }
        __syncthreads();
        if (tid == 0) g_cnt[blockIdx.x] = 0;
    }
}

extern "C" void kernel_launch(void* const* d_in, const int* in_sizes, int n_in,
                              void* d_out, int out_size) {
    const float* x  = (const float*)d_in[0];   // [4096, 64]
    const float* X  = (const float*)d_in[1];   // [50000, 64]
    const float* bw = (const float*)d_in[2];   // [1]

    prep_all<<<NPAD / 32 + MM / 32, 256>>>(x, X, bw);   // 1696 blocks

    dim3 grid(MM / MT, NSPLIT);                         // (64, 23)
    kde_main2<<<grid, 288>>>(bw, (float*)d_out);
}

// round 8
// speedup vs baseline: 1.2171x; 1.2171x over previous
#include <cuda_runtime.h>
#include <cuda_bf16.h>
#include <cstdint>

// GaussianKernelDensity: out[m] = coeff + logsumexp_n( -||x_m - X_n||^2 / (2 b^2) )
// M=4096, N=50000, D=64.
//  Launch 1: prep_all — pack x,X to bf16; fold norms+bandwidth into constants.
//  Launch 2: kde_main — 9 warps/CTA: warp 8 = cp.async producer filling a
//            2-stage B ring guarded by full/empty mbarriers; warps 0-7 =
//            consumers: bf16 HMMA + epilogue e = ex2.approx(v) on the MUFU
//            pipe (v = acc*inv4 + colc + rowc via one packed f32x2 fma).
//            No clamp needed: ex2.approx.ftz underflows to 0 for pad columns.

#define MM 4096
#define NN 50000
#define DD 64
#define NPAD 50176
#define NSPLIT 23
#define CHUNK 2176              // 17 * 128
#define NTILES 17
#define MT 64
#define NT 128
#define STAGE 16384             // 128 rows * 128 B

// device scratch
__device__ __nv_bfloat16 g_Xb[NPAD * DD];
__device__ float         g_CT[NPAD];       // -|X_n|^2 * inv2  (pad rows: -1000)
__device__ __nv_bfloat16 g_xb[MM * DD];
__device__ float         g_RT[MM];         // -|x_m|^2 * inv2 + 38
__device__ float         g_part[NSPLIT * MM];
__device__ int           g_cnt[MM / MT];

#define LDSM4(r0, r1, r2, r3, addr)                                              \
    asm volatile("ldmatrix.sync.aligned.m8n8.x4.shared.b16 {%0,%1,%2,%3}, [%4];" \
                 : "=r"(r0), "=r"(r1), "=r"(r2), "=r"(r3) : "r"(addr))

__device__ __forceinline__ void cp16(uint32_t dst, const void* src) {
    asm volatile("cp.async.cg.shared.global [%0], [%1], 16;" :: "r"(dst), "l"(src));
}
__device__ __forceinline__ uint32_t smem_u32(const void* p) {
    return (uint32_t)__cvta_generic_to_shared(p);
}
__device__ __forceinline__ void mbar_init(uint32_t a, uint32_t cnt) {
    asm volatile("mbarrier.init.shared.b64 [%0], %1;" :: "r"(a), "r"(cnt) : "memory");
}
__device__ __forceinline__ void mbar_arrive(uint32_t a) {
    asm volatile("mbarrier.arrive.shared.b64 _, [%0];" :: "r"(a) : "memory");
}
__device__ __forceinline__ void cp_async_mbar_arrive(uint32_t a) {
    asm volatile("cp.async.mbarrier.arrive.noinc.shared.b64 [%0];" :: "r"(a) : "memory");
}
__device__ __forceinline__ void mbar_wait(uint32_t a, uint32_t parity) {
    asm volatile(
        "{\n\t.reg .pred P;\n\t"
        "WL_%=:\n\t"
        "mbarrier.try_wait.parity.shared.b64 P, [%0], %1;\n\t"
        "@!P bra WL_%=;\n\t"
        "}" :: "r"(a), "r"(parity) : "memory");
}
__device__ __forceinline__ float ex2(float x) {
    float r;
    asm("ex2.approx.ftz.f32 %0, %1;" : "=f"(r) : "f"(x));
    return r;
}

// ---- packed f32x2 helpers (Blackwell) ----
__device__ __forceinline__ uint64_t pk2(float lo, float hi) {
    uint64_t r;
    asm("mov.b64 %0, {%1, %2};" : "=l"(r) : "f"(lo), "f"(hi));
    return r;
}
__device__ __forceinline__ void upk2(uint32_t& lo, uint32_t& hi, uint64_t v) {
    asm("mov.b64 {%0, %1}, %2;" : "=r"(lo), "=r"(hi) : "l"(v));
}
__device__ __forceinline__ uint64_t fma2(uint64_t a, uint64_t b, uint64_t c) {
    uint64_t d;
    asm("fma.rn.f32x2 %0, %1, %2, %3;" : "=l"(d) : "l"(a), "l"(b), "l"(c));
    return d;
}
__device__ __forceinline__ uint64_t add2(uint64_t a, uint64_t b) {
    uint64_t d;
    asm("add.rn.f32x2 %0, %1, %2;" : "=l"(d) : "l"(a), "l"(b));
    return d;
}

// ---------------- prep: pack + fold constants ----------------
__global__ void prep_all(const float* __restrict__ xin,
                         const float* __restrict__ Xin,
                         const float* __restrict__ bw) {
    const float b = bw[0];
    const float inv2 = 1.4426950408889634f / (2.f * b * b);   // log2e / (2 b^2)
    const int blk = blockIdx.x, tid = threadIdx.x;
    const int l8 = tid & 7;

    if (blk < NPAD / 32) {                       // X rows (incl. pad)
        int row = blk * 32 + (tid >> 3);
        uint4 packed = make_uint4(0u, 0u, 0u, 0u);
        __nv_bfloat16* hp = reinterpret_cast<__nv_bfloat16*>(&packed);
        float ss = 0.f;
        if (row < NN) {
            const float4* s4 = reinterpret_cast<const float4*>(Xin + row * DD + l8 * 8);
            float4 a = s4[0], d = s4[1];
            ss = a.x*a.x + a.y*a.y + a.z*a.z + a.w*a.w
               + d.x*d.x + d.y*d.y + d.z*d.z + d.w*d.w;
            hp[0] = __float2bfloat16_rn(a.x); hp[1] = __float2bfloat16_rn(a.y);
            hp[2] = __float2bfloat16_rn(a.z); hp[3] = __float2bfloat16_rn(a.w);
            hp[4] = __float2bfloat16_rn(d.x); hp[5] = __float2bfloat16_rn(d.y);
            hp[6] = __float2bfloat16_rn(d.z); hp[7] = __float2bfloat16_rn(d.w);
        }
        *reinterpret_cast<uint4*>(&g_Xb[row * DD + l8 * 8]) = packed;
        ss += __shfl_xor_sync(0xffffffffu, ss, 1);
        ss += __shfl_xor_sync(0xffffffffu, ss, 2);
        ss += __shfl_xor_sync(0xffffffffu, ss, 4);
        if (l8 == 0) g_CT[row] = (row < NN) ? (-ss * inv2) : -1000.f;
    } else {                                     // x rows
        int row = (blk - NPAD / 32) * 32 + (tid >> 3);
        const float4* s4 = reinterpret_cast<const float4*>(xin + row * DD + l8 * 8);
        float4 a = s4[0], d = s4[1];
        float ss = a.x*a.x + a.y*a.y + a.z*a.z + a.w*a.w
                 + d.x*d.x + d.y*d.y + d.z*d.z + d.w*d.w;
        uint4 packed;
        __nv_bfloat16* hp = reinterpret_cast<__nv_bfloat16*>(&packed);
        hp[0] = __float2bfloat16_rn(a.x); hp[1] = __float2bfloat16_rn(a.y);
        hp[2] = __float2bfloat16_rn(a.z); hp[3] = __float2bfloat16_rn(a.w);
        hp[4] = __float2bfloat16_rn(d.x); hp[5] = __float2bfloat16_rn(d.y);
        hp[6] = __float2bfloat16_rn(d.z); hp[7] = __float2bfloat16_rn(d.w);
        *reinterpret_cast<uint4*>(&g_xb[row * DD + l8 * 8]) = packed;
        ss += __shfl_xor_sync(0xffffffffu, ss, 1);
        ss += __shfl_xor_sync(0xffffffffu, ss, 2);
        ss += __shfl_xor_sync(0xffffffffu, ss, 4);
        if (l8 == 0) g_RT[row] = -ss * inv2 + 38.f;
    }
}

// ---------------- main: producer/consumer GEMM + MUFU exp2 sum ----------------
__global__ __launch_bounds__(288, 2) void kde_main(const float* __restrict__ bw,
                                                   float* __restrict__ out) {
    __shared__ __align__(1024) char S[2 * STAGE];            // 32KB B ring
    __shared__ __align__(1024) char XS[MT * 128];            //  8KB x tile (swizzled)
    __shared__ __align__(8) uint64_t mbars[4];               // full0,full1,empty0,empty1
    __shared__ float red[4][MT];
    __shared__ int sdone_flag;

    const int tid  = threadIdx.x;
    const int warp = tid >> 5;
    const int lane = tid & 31;

    const int m0    = blockIdx.x * MT;
    const int split = blockIdx.y;
    const int n0    = split * CHUNK;

    const uint32_t Sb = smem_u32(S);
    const uint32_t fullA[2]  = { smem_u32(&mbars[0]), smem_u32(&mbars[1]) };
    const uint32_t emptyA[2] = { smem_u32(&mbars[2]), smem_u32(&mbars[3]) };

    if (tid == 0) {
        mbar_init(fullA[0], 32); mbar_init(fullA[1], 32);
        mbar_init(emptyA[0], 8); mbar_init(emptyA[1], 8);
    }

    // consumers (256 threads) stage the x tile, swizzled
    if (warp < 8) {
        int row = tid >> 2, q = tid & 3;
        const uint4* s = reinterpret_cast<const uint4*>(g_xb + (m0 + row) * DD + q * 16);
        uint4 v0 = s[0], v1 = s[1];
        int base = row * 128;
        int msk = row & 7;
        *reinterpret_cast<uint4*>(XS + base + (((2 * q)     ^ msk) * 16)) = v0;
        *reinterpret_cast<uint4*>(XS + base + (((2 * q + 1) ^ msk) * 16)) = v1;
    }
    __syncthreads();   // mbarriers initialized + x tile visible

    if (warp == 8) {
        // ================= producer warp =================
        const int r0 = lane >> 3, ch = lane & 7;
        const __nv_bfloat16* src = g_Xb + (n0 + r0) * DD + ch * 8;
        const uint32_t de  = (uint32_t)(r0 * 128 + ((ch ^ r0) * 16));
        const uint32_t dof = (uint32_t)(r0 * 128 + 512 + ((ch ^ r0 ^ 4) * 16));
        for (int it = 0; it < NTILES; it++) {
            const int st = it & 1;
            if (it >= 2) mbar_wait(emptyA[st], ((it - 2) >> 1) & 1);
            const uint32_t base = Sb + (uint32_t)st * STAGE;
            #pragma unroll
            for (int q = 0; q < 32; q += 2) {
                cp16(base + q * 512 + de,  src);  src += 4 * DD;
                cp16(base + q * 512 + dof, src);  src += 4 * DD;
            }
            cp_async_mbar_arrive(fullA[st]);
        }
    } else {
        // ================= consumer warps =================
        const int g = lane >> 2;
        const int c = lane & 3;
        const int wm = warp >> 2;     // 0..1 (M)
        const int wn = warp & 3;      // 0..3 (N)

        const float b    = bw[0];
        const float inv4 = 1.4426950408889634f / (b * b);   // log2e / b^2

        // A fragments for the whole lifetime
        const int lr = (lane & 7) + ((lane >> 3) & 1) * 8;
        const int cb = lane >> 4;
        uint32_t afr[4][8];
        #pragma unroll
        for (int i = 0; i < 2; i++) {
            int rowp = wm * 32 + i * 16 + lr;
            uint32_t rb = smem_u32(XS) + rowp * 128;
            int rm = rowp & 7;
            #pragma unroll
            for (int ks = 0; ks < 4; ks++) {
                uint32_t a0, a1, a2, a3;
                LDSM4(a0, a1, a2, a3, rb + (((ks * 2 + cb) ^ rm) * 16));
                afr[ks][i * 4 + 0] = a0; afr[ks][i * 4 + 1] = a1;
                afr[ks][i * 4 + 2] = a2; afr[ks][i * 4 + 3] = a3;
            }
        }

        uint32_t rB_off[2]; int rB_msk[2];
        #pragma unroll
        for (int h = 0; h < 2; h++) {
            int rowp = wn * 32 + h * 16 + lr;
            rB_off[h] = (uint32_t)(rowp * 128);
            rB_msk[h] = rowp & 7;
        }

        uint64_t rc2[4];
        #pragma unroll
        for (int r = 0; r < 4; r++) {
            int rl = wm * 32 + (r >> 1) * 16 + (r & 1) * 8 + g;
            float rv = g_RT[m0 + rl];
            rc2[r] = pk2(rv, rv);
        }
        const uint64_t inv42 = pk2(inv4, inv4);

        const float* gc = g_CT + n0 + wn * 32 + 2 * c;
        float2 cv[4];
        #pragma unroll
        for (int j = 0; j < 4; j++) cv[j] = __ldg((const float2*)(gc + j * 8));

        float sum[4] = {0.f, 0.f, 0.f, 0.f};

        for (int it = 0; it < NTILES; it++) {
            const int st = it & 1;
            const uint32_t stb = Sb + (uint32_t)st * STAGE;
            mbar_wait(fullA[st], (it >> 1) & 1);

            uint64_t cc2[4];
            #pragma unroll
            for (int j = 0; j < 4; j++) cc2[j] = pk2(cv[j].x, cv[j].y);
            const int pf = (it + 1 < NTILES) ? it + 1 : it;
            #pragma unroll
            for (int j = 0; j < 4; j++)
                cv[j] = __ldg((const float2*)(gc + pf * NT + j * 8));

            #pragma unroll
            for (int h = 0; h < 2; h++) {
                float acc[2][2][4];
                #pragma unroll
                for (int i = 0; i < 2; i++)
                    #pragma unroll
                    for (int jn = 0; jn < 2; jn++)
                        #pragma unroll
                        for (int q = 0; q < 4; q++) acc[i][jn][q] = 0.f;

                #pragma unroll
                for (int ks = 0; ks < 4; ks++) {
                    uint32_t b0, b1, b2, b3;
                    uint32_t addr = stb + rB_off[h] + (((ks * 2 + cb) ^ rB_msk[h]) * 16);
                    LDSM4(b0, b1, b2, b3, addr);
                    #pragma unroll
                    for (int i = 0; i < 2; i++) {
                        asm volatile(
                            "mma.sync.aligned.m16n8k16.row.col.f32.bf16.bf16.f32 "
                            "{%0,%1,%2,%3}, {%4,%5,%6,%7}, {%8,%9}, {%0,%1,%2,%3};"
                            : "+f"(acc[i][0][0]), "+f"(acc[i][0][1]),
                              "+f"(acc[i][0][2]), "+f"(acc[i][0][3])
                            : "r"(afr[ks][i * 4 + 0]), "r"(afr[ks][i * 4 + 1]),
                              "r"(afr[ks][i * 4 + 2]), "r"(afr[ks][i * 4 + 3]),
                              "r"(b0), "r"(b2));
                        asm volatile(
                            "mma.sync.aligned.m16n8k16.row.col.f32.bf16.bf16.f32 "
                            "{%0,%1,%2,%3}, {%4,%5,%6,%7}, {%8,%9}, {%0,%1,%2,%3};"
                            : "+f"(acc[i][1][0]), "+f"(acc[i][1][1]),
                              "+f"(acc[i][1][2]), "+f"(acc[i][1][3])
                            : "r"(afr[ks][i * 4 + 0]), "r"(afr[ks][i * 4 + 1]),
                              "r"(afr[ks][i * 4 + 2]), "r"(afr[ks][i * 4 + 3]),
                              "r"(b1), "r"(b3));
                    }
                }

                // epilogue: v = acc*inv4 + (colc + rowc); e = ex2.approx(v).
                // Pad columns give v ~ -1000 -> ex2 underflows to exactly 0.
                #pragma unroll
                for (int r = 0; r < 4; r++) {
                    const int i = r >> 1, hf = r & 1;
                    #pragma unroll
                    for (int jn = 0; jn < 2; jn++) {
                        uint64_t ccr = add2(cc2[2 * h + jn], rc2[r]);
                        uint64_t a2  = pk2(acc[i][jn][hf * 2], acc[i][jn][hf * 2 + 1]);
                        uint64_t v2  = fma2(a2, inv42, ccr);
                        uint32_t vlo, vhi;
                        upk2(vlo, vhi, v2);
                        sum[r] += ex2(__uint_as_float(vlo));
                        sum[r] += ex2(__uint_as_float(vhi));
                    }
                }
            }

            if (lane == 0) mbar_arrive(emptyA[st]);
        }

        // quad reduce, store to red[] (each warp owns red[wn][wm*32..wm*32+31])
        #pragma unroll
        for (int r = 0; r < 4; r++) {
            float sv = sum[r];
            sv += __shfl_xor_sync(0xffffffffu, sv, 1);
            sv += __shfl_xor_sync(0xffffffffu, sv, 2);
            if (c == 0) {
                int rl = wm * 32 + (r >> 1) * 16 + (r & 1) * 8 + g;
                red[wn][rl] = sv;
            }
        }
    }

    __syncthreads();
    if (tid < MT) {
        float tot = red[0][tid] + red[1][tid] + red[2][tid] + red[3][tid];
        g_part[split * MM + m0 + tid] = tot;
    }
    __syncthreads();

    // ---- tail CTA per m-block merges the 23 split sums ----
    if (tid == 0) {
        __threadfence();
        int old = atomicAdd(&g_cnt[blockIdx.x], 1);
        sdone_flag = (old == NSPLIT - 1) ? 1 : 0;
        if (sdone_flag) __threadfence();
    }
    __syncthreads();
    if (sdone_flag) {
        if (tid < MT) {
            float tot = 0.f;
            #pragma unroll
            for (int s = 0; s < NSPLIT; s++) tot += __ldcg(&g_part[s * MM + m0 + tid]);
            // coeff = -ln(50000) - 32*ln(2*pi)
            out[m0 + tid] = -69.63184443f
                          + (log2f(tot) - 38.f) * 0.6931471805599453f;
        }
        __syncthreads();
        if (tid == 0) g_cnt[blockIdx.x] = 0;   // reset for next graph replay
    }
}

extern "C" void kernel_launch(void* const* d_in, const int* in_sizes, int n_in,
                              void* d_out, int out_size) {
    const float* x  = (const float*)d_in[0];   // [4096, 64]
    const float* X  = (const float*)d_in[1];   // [50000, 64]
    const float* bw = (const float*)d_in[2];   // [1]

    prep_all<<<NPAD / 32 + MM / 32, 256>>>(x, X, bw);   // 1696 blocks

    dim3 grid(MM / MT, NSPLIT);                         // (64, 23)
    kde_main<<<grid, 288>>>(bw, (float*)d_out);
}